// round 4
// baseline (speedup 1.0000x reference)
#include <cuda_runtime.h>
#include <math.h>

#define B_SZ 4096
#define D_SZ 32
#define H_SZ 1024
#define K_SZ 1024
#define MT   (B_SZ * D_SZ)   /* 131072 tangent rows (b,d) */

// ---------------- scratch (static device globals; no allocs) ----------------
__device__ float g_h1[B_SZ * H_SZ];                 // 16 MB
__device__ float g_h2[B_SZ * H_SZ];                 // 16 MB
__device__ float g_h3[B_SZ * H_SZ];                 // 16 MB
__device__ float g_U2[(size_t)MT * H_SZ];           // 512 MB
__device__ float g_tpart[8 * B_SZ];                 // per-(jtile, sample) trace partials

// ---------------- GEMM tiling ----------------
#define BM 128
#define BN 128
#define BK 16

__device__ __forceinline__ void sts_tile(float (*dst)[BM], const float4* v, int tid) {
#pragma unroll
    for (int l = 0; l < 2; l++) {
        int f = tid * 2 + l;
        int r = f >> 2, kq = f & 3;
        dst[kq * 4 + 0][r] = v[l].x;
        dst[kq * 4 + 1][r] = v[l].y;
        dst[kq * 4 + 2][r] = v[l].z;
        dst[kq * 4 + 3][r] = v[l].w;
    }
}

__device__ __forceinline__ void sts_t1(float (*dst)[BM], const float* v, int tid) {
#pragma unroll
    for (int i = 0; i < 8; i++) {
        int e = tid + i * 256;
        dst[e >> 7][e & 127] = v[i];
    }
}

// MODE 0: C = tanh(A @ W^T + bias)                     (forward hidden layers)
// MODE 1: C(=U2) = (1-hs^2) .* (U1 @ W^T), U1 generated on the fly from A(=h1), W0
// MODE 2: trace partials from (1-hs^2) .* (A(=U2) @ W^T) dotted with W3 rows
template <int MODE>
__global__ void __launch_bounds__(256, 2)
gemm_kernel(const float* __restrict__ A, const float* __restrict__ W,
            const float* __restrict__ bias, const float* __restrict__ hs,
            const float* __restrict__ W0p, const float* __restrict__ W3p,
            float* __restrict__ C)
{
    __shared__ float As[2][BK][BM];
    __shared__ float Bs[2][BK][BN];
    __shared__ float red[256];

    const int tid = threadIdx.x;
    const int tx = tid & 15, ty = tid >> 4;
    const int rowBase = blockIdx.y * BM;
    const int colBase = blockIdx.x * BN;

    float acc[8][8];
#pragma unroll
    for (int i = 0; i < 8; i++)
#pragma unroll
        for (int j = 0; j < 8; j++) acc[i][j] = 0.0f;

    // ---- prologue: load k-tile 0 into smem buffer 0 ----
    {
        float4 pb[2];
        if (MODE == 1) {
            float pt[8];
#pragma unroll
            for (int i = 0; i < 8; i++) {
                int e = tid + i * 256;
                int r = e & 127, kk = e >> 7;
                int grow = rowBase + r;
                float h = A[(size_t)(grow >> 5) * H_SZ + kk];
                pt[i] = (1.0f - h * h) * W0p[kk * 33 + (grow & 31)];
            }
            sts_t1(As[0], pt, tid);
        } else {
            float4 pa[2];
#pragma unroll
            for (int l = 0; l < 2; l++) {
                int f = tid * 2 + l;
                int r = f >> 2, kq = f & 3;
                pa[l] = *reinterpret_cast<const float4*>(A + (size_t)(rowBase + r) * K_SZ + kq * 4);
            }
            sts_tile(As[0], pa, tid);
        }
#pragma unroll
        for (int l = 0; l < 2; l++) {
            int f = tid * 2 + l;
            int r = f >> 2, kq = f & 3;
            pb[l] = *reinterpret_cast<const float4*>(W + (size_t)(colBase + r) * K_SZ + kq * 4);
        }
        sts_tile(Bs[0], pb, tid);
    }
    __syncthreads();

    // ---- main loop: double-buffered over 64 k-tiles ----
    const int NKT = K_SZ / BK;
    int cur = 0;
    for (int kt = 0; kt < NKT; kt++) {
        float4 na[2];
        float  nt[8];
        float4 nb[2];
        if (kt + 1 < NKT) {
            const int k0 = (kt + 1) * BK;
            if (MODE == 1) {
#pragma unroll
                for (int i = 0; i < 8; i++) {
                    int e = tid + i * 256;
                    int r = e & 127, kk = e >> 7;
                    int gk = k0 + kk;
                    int grow = rowBase + r;
                    float h = A[(size_t)(grow >> 5) * H_SZ + gk];
                    nt[i] = (1.0f - h * h) * W0p[gk * 33 + (grow & 31)];
                }
            } else {
#pragma unroll
                for (int l = 0; l < 2; l++) {
                    int f = tid * 2 + l;
                    int r = f >> 2, kq = f & 3;
                    na[l] = *reinterpret_cast<const float4*>(A + (size_t)(rowBase + r) * K_SZ + k0 + kq * 4);
                }
            }
#pragma unroll
            for (int l = 0; l < 2; l++) {
                int f = tid * 2 + l;
                int r = f >> 2, kq = f & 3;
                nb[l] = *reinterpret_cast<const float4*>(W + (size_t)(colBase + r) * K_SZ + k0 + kq * 4);
            }
        }

#pragma unroll
        for (int k = 0; k < BK; k++) {
            float av[8], bv[8];
            *reinterpret_cast<float4*>(&av[0]) = *reinterpret_cast<const float4*>(&As[cur][k][ty * 8]);
            *reinterpret_cast<float4*>(&av[4]) = *reinterpret_cast<const float4*>(&As[cur][k][ty * 8 + 4]);
            *reinterpret_cast<float4*>(&bv[0]) = *reinterpret_cast<const float4*>(&Bs[cur][k][tx * 8]);
            *reinterpret_cast<float4*>(&bv[4]) = *reinterpret_cast<const float4*>(&Bs[cur][k][tx * 8 + 4]);
#pragma unroll
            for (int i = 0; i < 8; i++)
#pragma unroll
                for (int j = 0; j < 8; j++)
                    acc[i][j] = fmaf(av[i], bv[j], acc[i][j]);
        }

        if (kt + 1 < NKT) {
            int nxt = cur ^ 1;
            if (MODE == 1) sts_t1(As[nxt], nt, tid);
            else           sts_tile(As[nxt], na, tid);
            sts_tile(Bs[nxt], nb, tid);
            __syncthreads();
            cur = nxt;
        }
    }

    // ---- epilogues ----
    if (MODE == 0) {
        const int c = colBase + tx * 8;
#pragma unroll
        for (int i = 0; i < 8; i++) {
            int r = rowBase + ty * 8 + i;
            float4 o0, o1;
            o0.x = tanhf(acc[i][0] + bias[c + 0]);
            o0.y = tanhf(acc[i][1] + bias[c + 1]);
            o0.z = tanhf(acc[i][2] + bias[c + 2]);
            o0.w = tanhf(acc[i][3] + bias[c + 3]);
            o1.x = tanhf(acc[i][4] + bias[c + 4]);
            o1.y = tanhf(acc[i][5] + bias[c + 5]);
            o1.z = tanhf(acc[i][6] + bias[c + 6]);
            o1.w = tanhf(acc[i][7] + bias[c + 7]);
            *reinterpret_cast<float4*>(C + (size_t)r * H_SZ + c)     = o0;
            *reinterpret_cast<float4*>(C + (size_t)r * H_SZ + c + 4) = o1;
        }
    } else if (MODE == 1) {
        const int bglob = (rowBase >> 5) + (ty >> 2);  // all 8 rows of this thread share one sample
        const int c = colBase + tx * 8;
        float sv[8];
#pragma unroll
        for (int j = 0; j < 8; j++) {
            float h = hs[(size_t)bglob * H_SZ + c + j];
            sv[j] = 1.0f - h * h;
        }
#pragma unroll
        for (int i = 0; i < 8; i++) {
            int r = rowBase + ty * 8 + i;
            float4 o0, o1;
            o0.x = acc[i][0] * sv[0];
            o0.y = acc[i][1] * sv[1];
            o0.z = acc[i][2] * sv[2];
            o0.w = acc[i][3] * sv[3];
            o1.x = acc[i][4] * sv[4];
            o1.y = acc[i][5] * sv[5];
            o1.z = acc[i][6] * sv[6];
            o1.w = acc[i][7] * sv[7];
            size_t base = (size_t)r * H_SZ + c;
            *reinterpret_cast<float4*>(C + base)     = o0;
            *reinterpret_cast<float4*>(C + base + 4) = o1;
        }
    } else {
        const int bglob = (rowBase >> 5) + (ty >> 2);
        float part = 0.0f;
#pragma unroll
        for (int j = 0; j < 8; j++) {
            int c = colBase + tx * 8 + j;
            float h = hs[(size_t)bglob * H_SZ + c];
            float s = 1.0f - h * h;
#pragma unroll
            for (int i = 0; i < 8; i++) {
                int d = (ty * 8 + i) & 31;
                part += W3p[d * H_SZ + c] * (acc[i][j] * s);
            }
        }
        red[tid] = part;
        __syncthreads();
        if (tid < 4) {
            float ssum = 0.0f;
#pragma unroll 8
            for (int t = 0; t < 64; t++) ssum += red[tid * 64 + t];
            // unique (jtile, sample) slot -> deterministic, no atomics
            g_tpart[blockIdx.x * B_SZ + (rowBase >> 5) + tid] = ssum;
        }
    }
}

// ---------------- small kernels ----------------

// h1 = tanh([z|t] @ W0^T + b0)
__global__ void layer0_kernel(const float* __restrict__ t, const float* __restrict__ z,
                              const float* __restrict__ W0, const float* __restrict__ b0,
                              float* __restrict__ h1)
{
    int idx = blockIdx.x * blockDim.x + threadIdx.x;   // B*H
    int j = idx & (H_SZ - 1);
    int b = idx >> 10;
    const float* w  = W0 + j * 33;
    const float* zr = z + b * D_SZ;
    float acc = b0[j] + t[0] * w[32];
#pragma unroll
    for (int d = 0; d < 32; d++) acc = fmaf(zr[d], w[d], acc);
    h1[idx] = tanhf(acc);
}

// out = h3 @ W3^T + b3
__global__ void out_kernel(const float* __restrict__ h3, const float* __restrict__ W3,
                           const float* __restrict__ b3, float* __restrict__ out)
{
    int idx = blockIdx.x * blockDim.x + threadIdx.x;   // B*D
    int d = idx & 31;
    int b = idx >> 5;
    const float* h = h3 + (size_t)b * H_SZ;
    const float* w = W3 + (size_t)d * H_SZ;
    float acc = 0.0f;
#pragma unroll 8
    for (int k = 0; k < H_SZ; k++) acc = fmaf(h[k], w[k], acc);
    out[idx] = acc + b3[d];
}

// divv[b] = -(sum of 8 j-tile partials)
__global__ void fin_kernel(float* __restrict__ out)
{
    int b = blockIdx.x * blockDim.x + threadIdx.x;
    if (b < B_SZ) {
        float s = 0.0f;
#pragma unroll
        for (int x = 0; x < 8; x++) s += g_tpart[x * B_SZ + b];
        out[B_SZ * D_SZ + b] = -s;
    }
}

// ---------------- launch ----------------
extern "C" void kernel_launch(void* const* d_in, const int* in_sizes, int n_in,
                              void* d_out, int out_size)
{
    const float* t  = (const float*)d_in[0];
    const float* z  = (const float*)d_in[1];
    const float* W0 = (const float*)d_in[2];
    const float* b0 = (const float*)d_in[3];
    const float* W1 = (const float*)d_in[4];
    const float* b1 = (const float*)d_in[5];
    const float* W2 = (const float*)d_in[6];
    const float* b2 = (const float*)d_in[7];
    const float* W3 = (const float*)d_in[8];
    const float* b3 = (const float*)d_in[9];
    float* out = (float*)d_out;

    float *ph1, *ph2, *ph3, *pU2;
    cudaGetSymbolAddress((void**)&ph1, g_h1);
    cudaGetSymbolAddress((void**)&ph2, g_h2);
    cudaGetSymbolAddress((void**)&ph3, g_h3);
    cudaGetSymbolAddress((void**)&pU2, g_U2);

    // forward
    layer0_kernel<<<(B_SZ * H_SZ) / 256, 256>>>(t, z, W0, b0, ph1);
    dim3 gF(H_SZ / BN, B_SZ / BM);           // (8, 32)
    gemm_kernel<0><<<gF, 256>>>(ph1, W1, b1, nullptr, nullptr, nullptr, ph2);
    gemm_kernel<0><<<gF, 256>>>(ph2, W2, b2, nullptr, nullptr, nullptr, ph3);
    out_kernel<<<(B_SZ * D_SZ) / 256, 256>>>(ph3, W3, b3, out);

    // tangent (JVP) chain: U2 = (1-h2^2) .* ((a1 .* W0') @ W1^T); trace from W2/W3
    dim3 gT(H_SZ / BN, MT / BM);             // (8, 1024)
    gemm_kernel<1><<<gT, 256>>>(ph1, W1, nullptr, ph2, W0, nullptr, pU2);
    gemm_kernel<2><<<gT, 256>>>(pU2, W2, nullptr, ph3, nullptr, W3, nullptr);

    fin_kernel<<<(B_SZ + 255) / 256, 256>>>(out);
}

// round 5
// speedup vs baseline: 1.0015x; 1.0015x over previous
#include <cuda_runtime.h>
#include <math.h>

#define B_SZ 4096
#define D_SZ 32
#define H_SZ 1024
#define K_SZ 1024
#define MT   (B_SZ * D_SZ)   /* 131072 tangent rows (b,d) */

// ---------------- scratch (static device globals; no allocs) ----------------
__device__ float g_h1[B_SZ * H_SZ];                 // 16 MB
__device__ float g_h2[B_SZ * H_SZ];                 // 16 MB
__device__ float g_h3[B_SZ * H_SZ];                 // 16 MB
__device__ float g_U2[(size_t)MT * H_SZ];           // 512 MB
__device__ float g_tpart[8 * B_SZ];                 // per-(jtile, sample) trace partials

// ---------------- GEMM tiling ----------------
#define BM 128
#define BN 128
#define BK 16

__device__ __forceinline__ void sts_tile(float (*dst)[BM], const float4* v, int tid) {
#pragma unroll
    for (int l = 0; l < 2; l++) {
        int f = tid * 2 + l;
        int r = f >> 2, kq = f & 3;
        dst[kq * 4 + 0][r] = v[l].x;
        dst[kq * 4 + 1][r] = v[l].y;
        dst[kq * 4 + 2][r] = v[l].z;
        dst[kq * 4 + 3][r] = v[l].w;
    }
}

__device__ __forceinline__ void sts_t1(float (*dst)[BM], const float* v, int tid) {
#pragma unroll
    for (int i = 0; i < 8; i++) {
        int e = tid + i * 256;
        dst[e >> 7][e & 127] = v[i];
    }
}

// MODE 0: C = tanh(A @ W^T + bias)                     (forward hidden layers)
// MODE 1: C(=U2) = (1-hs^2) .* (U1 @ W^T), U1 generated on the fly from A(=h1), W0
// MODE 2: trace partials from (1-hs^2) .* (A(=U2) @ W^T) dotted with W3 rows
template <int MODE>
__global__ void __launch_bounds__(256, 2)
gemm_kernel(const float* __restrict__ A, const float* __restrict__ W,
            const float* __restrict__ bias, const float* __restrict__ hs,
            const float* __restrict__ W0p, const float* __restrict__ W3p,
            float* __restrict__ C)
{
    __shared__ float As[2][BK][BM];
    __shared__ float Bs[2][BK][BN];
    __shared__ float red[256];

    const int tid = threadIdx.x;
    const int tx = tid & 15, ty = tid >> 4;
    const int rowBase = blockIdx.y * BM;
    const int colBase = blockIdx.x * BN;

    float acc[8][8];
#pragma unroll
    for (int i = 0; i < 8; i++)
#pragma unroll
        for (int j = 0; j < 8; j++) acc[i][j] = 0.0f;

    // ---- prologue: load k-tile 0 into smem buffer 0 ----
    {
        float4 pb[2];
        if (MODE == 1) {
            float pt[8];
#pragma unroll
            for (int i = 0; i < 8; i++) {
                int e = tid + i * 256;
                int r = e & 127, kk = e >> 7;
                int grow = rowBase + r;
                float h = A[(size_t)(grow >> 5) * H_SZ + kk];
                pt[i] = (1.0f - h * h) * W0p[kk * 33 + (grow & 31)];
            }
            sts_t1(As[0], pt, tid);
        } else {
            float4 pa[2];
#pragma unroll
            for (int l = 0; l < 2; l++) {
                int f = tid * 2 + l;
                int r = f >> 2, kq = f & 3;
                pa[l] = *reinterpret_cast<const float4*>(A + (size_t)(rowBase + r) * K_SZ + kq * 4);
            }
            sts_tile(As[0], pa, tid);
        }
#pragma unroll
        for (int l = 0; l < 2; l++) {
            int f = tid * 2 + l;
            int r = f >> 2, kq = f & 3;
            pb[l] = *reinterpret_cast<const float4*>(W + (size_t)(colBase + r) * K_SZ + kq * 4);
        }
        sts_tile(Bs[0], pb, tid);
    }
    __syncthreads();

    // ---- main loop: double-buffered over 64 k-tiles ----
    const int NKT = K_SZ / BK;
    int cur = 0;
    for (int kt = 0; kt < NKT; kt++) {
        float4 na[2];
        float  nt[8];
        float4 nb[2];
        if (kt + 1 < NKT) {
            const int k0 = (kt + 1) * BK;
            if (MODE == 1) {
#pragma unroll
                for (int i = 0; i < 8; i++) {
                    int e = tid + i * 256;
                    int r = e & 127, kk = e >> 7;
                    int gk = k0 + kk;
                    int grow = rowBase + r;
                    float h = A[(size_t)(grow >> 5) * H_SZ + gk];
                    nt[i] = (1.0f - h * h) * W0p[gk * 33 + (grow & 31)];
                }
            } else {
#pragma unroll
                for (int l = 0; l < 2; l++) {
                    int f = tid * 2 + l;
                    int r = f >> 2, kq = f & 3;
                    na[l] = *reinterpret_cast<const float4*>(A + (size_t)(rowBase + r) * K_SZ + k0 + kq * 4);
                }
            }
#pragma unroll
            for (int l = 0; l < 2; l++) {
                int f = tid * 2 + l;
                int r = f >> 2, kq = f & 3;
                nb[l] = *reinterpret_cast<const float4*>(W + (size_t)(colBase + r) * K_SZ + k0 + kq * 4);
            }
        }

#pragma unroll
        for (int k = 0; k < BK; k++) {
            float av[8], bv[8];
            *reinterpret_cast<float4*>(&av[0]) = *reinterpret_cast<const float4*>(&As[cur][k][ty * 8]);
            *reinterpret_cast<float4*>(&av[4]) = *reinterpret_cast<const float4*>(&As[cur][k][ty * 8 + 4]);
            *reinterpret_cast<float4*>(&bv[0]) = *reinterpret_cast<const float4*>(&Bs[cur][k][tx * 8]);
            *reinterpret_cast<float4*>(&bv[4]) = *reinterpret_cast<const float4*>(&Bs[cur][k][tx * 8 + 4]);
#pragma unroll
            for (int i = 0; i < 8; i++)
#pragma unroll
                for (int j = 0; j < 8; j++)
                    acc[i][j] = fmaf(av[i], bv[j], acc[i][j]);
        }

        if (kt + 1 < NKT) {
            int nxt = cur ^ 1;
            if (MODE == 1) sts_t1(As[nxt], nt, tid);
            else           sts_tile(As[nxt], na, tid);
            sts_tile(Bs[nxt], nb, tid);
            __syncthreads();
            cur = nxt;
        }
    }

    // ---- epilogues ----
    if (MODE == 0) {
        const int c = colBase + tx * 8;
#pragma unroll
        for (int i = 0; i < 8; i++) {
            int r = rowBase + ty * 8 + i;
            float4 o0, o1;
            o0.x = tanhf(acc[i][0] + bias[c + 0]);
            o0.y = tanhf(acc[i][1] + bias[c + 1]);
            o0.z = tanhf(acc[i][2] + bias[c + 2]);
            o0.w = tanhf(acc[i][3] + bias[c + 3]);
            o1.x = tanhf(acc[i][4] + bias[c + 4]);
            o1.y = tanhf(acc[i][5] + bias[c + 5]);
            o1.z = tanhf(acc[i][6] + bias[c + 6]);
            o1.w = tanhf(acc[i][7] + bias[c + 7]);
            *reinterpret_cast<float4*>(C + (size_t)r * H_SZ + c)     = o0;
            *reinterpret_cast<float4*>(C + (size_t)r * H_SZ + c + 4) = o1;
        }
    } else if (MODE == 1) {
        const int bglob = (rowBase >> 5) + (ty >> 2);  // all 8 rows of this thread share one sample
        const int c = colBase + tx * 8;
        float sv[8];
#pragma unroll
        for (int j = 0; j < 8; j++) {
            float h = hs[(size_t)bglob * H_SZ + c + j];
            sv[j] = 1.0f - h * h;
        }
#pragma unroll
        for (int i = 0; i < 8; i++) {
            int r = rowBase + ty * 8 + i;
            float4 o0, o1;
            o0.x = acc[i][0] * sv[0];
            o0.y = acc[i][1] * sv[1];
            o0.z = acc[i][2] * sv[2];
            o0.w = acc[i][3] * sv[3];
            o1.x = acc[i][4] * sv[4];
            o1.y = acc[i][5] * sv[5];
            o1.z = acc[i][6] * sv[6];
            o1.w = acc[i][7] * sv[7];
            size_t base = (size_t)r * H_SZ + c;
            *reinterpret_cast<float4*>(C + base)     = o0;
            *reinterpret_cast<float4*>(C + base + 4) = o1;
        }
    } else {
        const int bglob = (rowBase >> 5) + (ty >> 2);
        float part = 0.0f;
#pragma unroll
        for (int j = 0; j < 8; j++) {
            int c = colBase + tx * 8 + j;
            float h = hs[(size_t)bglob * H_SZ + c];
            float s = 1.0f - h * h;
#pragma unroll
            for (int i = 0; i < 8; i++) {
                int d = (ty * 8 + i) & 31;
                part += W3p[d * H_SZ + c] * (acc[i][j] * s);
            }
        }
        red[tid] = part;
        __syncthreads();
        if (tid < 4) {
            float ssum = 0.0f;
#pragma unroll 8
            for (int t = 0; t < 64; t++) ssum += red[tid * 64 + t];
            // unique (jtile, sample) slot -> deterministic, no atomics
            g_tpart[blockIdx.x * B_SZ + (rowBase >> 5) + tid] = ssum;
        }
    }
}

// ---------------- small kernels ----------------

// h1 = tanh([z|t] @ W0^T + b0)
__global__ void layer0_kernel(const float* __restrict__ t, const float* __restrict__ z,
                              const float* __restrict__ W0, const float* __restrict__ b0,
                              float* __restrict__ h1)
{
    int idx = blockIdx.x * blockDim.x + threadIdx.x;   // B*H
    int j = idx & (H_SZ - 1);
    int b = idx >> 10;
    const float* w  = W0 + j * 33;
    const float* zr = z + b * D_SZ;
    float acc = b0[j] + t[0] * w[32];
#pragma unroll
    for (int d = 0; d < 32; d++) acc = fmaf(zr[d], w[d], acc);
    h1[idx] = tanhf(acc);
}

// out = h3 @ W3^T + b3
__global__ void out_kernel(const float* __restrict__ h3, const float* __restrict__ W3,
                           const float* __restrict__ b3, float* __restrict__ out)
{
    int idx = blockIdx.x * blockDim.x + threadIdx.x;   // B*D
    int d = idx & 31;
    int b = idx >> 5;
    const float* h = h3 + (size_t)b * H_SZ;
    const float* w = W3 + (size_t)d * H_SZ;
    float acc = 0.0f;
#pragma unroll 8
    for (int k = 0; k < H_SZ; k++) acc = fmaf(h[k], w[k], acc);
    out[idx] = acc + b3[d];
}

// divv[b] = -(sum of 8 j-tile partials)
__global__ void fin_kernel(float* __restrict__ out)
{
    int b = blockIdx.x * blockDim.x + threadIdx.x;
    if (b < B_SZ) {
        float s = 0.0f;
#pragma unroll
        for (int x = 0; x < 8; x++) s += g_tpart[x * B_SZ + b];
        out[B_SZ * D_SZ + b] = -s;
    }
}

// ---------------- launch ----------------
extern "C" void kernel_launch(void* const* d_in, const int* in_sizes, int n_in,
                              void* d_out, int out_size)
{
    const float* t  = (const float*)d_in[0];
    const float* z  = (const float*)d_in[1];
    const float* W0 = (const float*)d_in[2];
    const float* b0 = (const float*)d_in[3];
    const float* W1 = (const float*)d_in[4];
    const float* b1 = (const float*)d_in[5];
    const float* W2 = (const float*)d_in[6];
    const float* b2 = (const float*)d_in[7];
    const float* W3 = (const float*)d_in[8];
    const float* b3 = (const float*)d_in[9];
    float* out = (float*)d_out;

    float *ph1, *ph2, *ph3, *pU2;
    cudaGetSymbolAddress((void**)&ph1, g_h1);
    cudaGetSymbolAddress((void**)&ph2, g_h2);
    cudaGetSymbolAddress((void**)&ph3, g_h3);
    cudaGetSymbolAddress((void**)&pU2, g_U2);

    // forward
    layer0_kernel<<<(B_SZ * H_SZ) / 256, 256>>>(t, z, W0, b0, ph1);
    dim3 gF(H_SZ / BN, B_SZ / BM);           // (8, 32)
    gemm_kernel<0><<<gF, 256>>>(ph1, W1, b1, nullptr, nullptr, nullptr, ph2);
    gemm_kernel<0><<<gF, 256>>>(ph2, W2, b2, nullptr, nullptr, nullptr, ph3);
    out_kernel<<<(B_SZ * D_SZ) / 256, 256>>>(ph3, W3, b3, out);

    // tangent (JVP) chain: U2 = (1-h2^2) .* ((a1 .* W0') @ W1^T); trace from W2/W3
    dim3 gT(H_SZ / BN, MT / BM);             // (8, 1024)
    gemm_kernel<1><<<gT, 256>>>(ph1, W1, nullptr, ph2, W0, nullptr, pU2);
    gemm_kernel<2><<<gT, 256>>>(pU2, W2, nullptr, ph3, nullptr, W3, nullptr);

    fin_kernel<<<(B_SZ + 255) / 256, 256>>>(out);
}

// round 6
// speedup vs baseline: 1.0022x; 1.0007x over previous
#include <cuda_runtime.h>
#include <math.h>

#define B_SZ 4096
#define D_SZ 32
#define H_SZ 1024
#define K_SZ 1024
#define MT   (B_SZ * D_SZ)   /* 131072 tangent rows (b,d) */

// ---------------- scratch (static device globals; no allocs) ----------------
__device__ float g_h1[B_SZ * H_SZ];                 // 16 MB
__device__ float g_h2[B_SZ * H_SZ];                 // 16 MB
__device__ float g_h3[B_SZ * H_SZ];                 // 16 MB
__device__ float g_U2[(size_t)MT * H_SZ];           // 512 MB
__device__ float g_tpart[8 * B_SZ];                 // per-(jtile, sample) trace partials

// ---------------- GEMM tiling ----------------
#define BM 128
#define BN 128
#define BK 16

__device__ __forceinline__ void sts_tile(float (*dst)[BM], const float4* v, int tid) {
#pragma unroll
    for (int l = 0; l < 2; l++) {
        int f = tid * 2 + l;
        int r = f >> 2, kq = f & 3;
        dst[kq * 4 + 0][r] = v[l].x;
        dst[kq * 4 + 1][r] = v[l].y;
        dst[kq * 4 + 2][r] = v[l].z;
        dst[kq * 4 + 3][r] = v[l].w;
    }
}

__device__ __forceinline__ void sts_t1(float (*dst)[BM], const float* v, int tid) {
#pragma unroll
    for (int i = 0; i < 8; i++) {
        int e = tid + i * 256;
        dst[e >> 7][e & 127] = v[i];
    }
}

// MODE 0: C = tanh(A @ W^T + bias)                     (forward hidden layers)
// MODE 1: C(=U2) = (1-hs^2) .* (U1 @ W^T), U1 generated on the fly from A(=h1), W0
// MODE 2: trace partials from (1-hs^2) .* (A(=U2) @ W^T) dotted with W3 rows
template <int MODE>
__global__ void __launch_bounds__(256, 2)
gemm_kernel(const float* __restrict__ A, const float* __restrict__ W,
            const float* __restrict__ bias, const float* __restrict__ hs,
            const float* __restrict__ W0p, const float* __restrict__ W3p,
            float* __restrict__ C)
{
    __shared__ float As[2][BK][BM];
    __shared__ float Bs[2][BK][BN];
    __shared__ float red[256];

    const int tid = threadIdx.x;
    const int tx = tid & 15, ty = tid >> 4;
    const int rowBase = blockIdx.y * BM;
    const int colBase = blockIdx.x * BN;

    float acc[8][8];
#pragma unroll
    for (int i = 0; i < 8; i++)
#pragma unroll
        for (int j = 0; j < 8; j++) acc[i][j] = 0.0f;

    // ---- prologue: load k-tile 0 into smem buffer 0 ----
    {
        float4 pb[2];
        if (MODE == 1) {
            float pt[8];
#pragma unroll
            for (int i = 0; i < 8; i++) {
                int e = tid + i * 256;
                int r = e & 127, kk = e >> 7;
                int grow = rowBase + r;
                float h = A[(size_t)(grow >> 5) * H_SZ + kk];
                pt[i] = (1.0f - h * h) * W0p[kk * 33 + (grow & 31)];
            }
            sts_t1(As[0], pt, tid);
        } else {
            float4 pa[2];
#pragma unroll
            for (int l = 0; l < 2; l++) {
                int f = tid * 2 + l;
                int r = f >> 2, kq = f & 3;
                pa[l] = *reinterpret_cast<const float4*>(A + (size_t)(rowBase + r) * K_SZ + kq * 4);
            }
            sts_tile(As[0], pa, tid);
        }
#pragma unroll
        for (int l = 0; l < 2; l++) {
            int f = tid * 2 + l;
            int r = f >> 2, kq = f & 3;
            pb[l] = *reinterpret_cast<const float4*>(W + (size_t)(colBase + r) * K_SZ + kq * 4);
        }
        sts_tile(Bs[0], pb, tid);
    }
    __syncthreads();

    // ---- main loop: double-buffered over 64 k-tiles ----
    const int NKT = K_SZ / BK;
    int cur = 0;
    for (int kt = 0; kt < NKT; kt++) {
        float4 na[2];
        float  nt[8];
        float4 nb[2];
        if (kt + 1 < NKT) {
            const int k0 = (kt + 1) * BK;
            if (MODE == 1) {
#pragma unroll
                for (int i = 0; i < 8; i++) {
                    int e = tid + i * 256;
                    int r = e & 127, kk = e >> 7;
                    int gk = k0 + kk;
                    int grow = rowBase + r;
                    float h = A[(size_t)(grow >> 5) * H_SZ + gk];
                    nt[i] = (1.0f - h * h) * W0p[gk * 33 + (grow & 31)];
                }
            } else {
#pragma unroll
                for (int l = 0; l < 2; l++) {
                    int f = tid * 2 + l;
                    int r = f >> 2, kq = f & 3;
                    na[l] = *reinterpret_cast<const float4*>(A + (size_t)(rowBase + r) * K_SZ + k0 + kq * 4);
                }
            }
#pragma unroll
            for (int l = 0; l < 2; l++) {
                int f = tid * 2 + l;
                int r = f >> 2, kq = f & 3;
                nb[l] = *reinterpret_cast<const float4*>(W + (size_t)(colBase + r) * K_SZ + k0 + kq * 4);
            }
        }

#pragma unroll
        for (int k = 0; k < BK; k++) {
            float av[8], bv[8];
            *reinterpret_cast<float4*>(&av[0]) = *reinterpret_cast<const float4*>(&As[cur][k][ty * 8]);
            *reinterpret_cast<float4*>(&av[4]) = *reinterpret_cast<const float4*>(&As[cur][k][ty * 8 + 4]);
            *reinterpret_cast<float4*>(&bv[0]) = *reinterpret_cast<const float4*>(&Bs[cur][k][tx * 8]);
            *reinterpret_cast<float4*>(&bv[4]) = *reinterpret_cast<const float4*>(&Bs[cur][k][tx * 8 + 4]);
#pragma unroll
            for (int i = 0; i < 8; i++)
#pragma unroll
                for (int j = 0; j < 8; j++)
                    acc[i][j] = fmaf(av[i], bv[j], acc[i][j]);
        }

        if (kt + 1 < NKT) {
            int nxt = cur ^ 1;
            if (MODE == 1) sts_t1(As[nxt], nt, tid);
            else           sts_tile(As[nxt], na, tid);
            sts_tile(Bs[nxt], nb, tid);
            __syncthreads();
            cur = nxt;
        }
    }

    // ---- epilogues ----
    if (MODE == 0) {
        const int c = colBase + tx * 8;
#pragma unroll
        for (int i = 0; i < 8; i++) {
            int r = rowBase + ty * 8 + i;
            float4 o0, o1;
            o0.x = tanhf(acc[i][0] + bias[c + 0]);
            o0.y = tanhf(acc[i][1] + bias[c + 1]);
            o0.z = tanhf(acc[i][2] + bias[c + 2]);
            o0.w = tanhf(acc[i][3] + bias[c + 3]);
            o1.x = tanhf(acc[i][4] + bias[c + 4]);
            o1.y = tanhf(acc[i][5] + bias[c + 5]);
            o1.z = tanhf(acc[i][6] + bias[c + 6]);
            o1.w = tanhf(acc[i][7] + bias[c + 7]);
            *reinterpret_cast<float4*>(C + (size_t)r * H_SZ + c)     = o0;
            *reinterpret_cast<float4*>(C + (size_t)r * H_SZ + c + 4) = o1;
        }
    } else if (MODE == 1) {
        const int bglob = (rowBase >> 5) + (ty >> 2);  // all 8 rows of this thread share one sample
        const int c = colBase + tx * 8;
        float sv[8];
#pragma unroll
        for (int j = 0; j < 8; j++) {
            float h = hs[(size_t)bglob * H_SZ + c + j];
            sv[j] = 1.0f - h * h;
        }
#pragma unroll
        for (int i = 0; i < 8; i++) {
            int r = rowBase + ty * 8 + i;
            float4 o0, o1;
            o0.x = acc[i][0] * sv[0];
            o0.y = acc[i][1] * sv[1];
            o0.z = acc[i][2] * sv[2];
            o0.w = acc[i][3] * sv[3];
            o1.x = acc[i][4] * sv[4];
            o1.y = acc[i][5] * sv[5];
            o1.z = acc[i][6] * sv[6];
            o1.w = acc[i][7] * sv[7];
            size_t base = (size_t)r * H_SZ + c;
            *reinterpret_cast<float4*>(C + base)     = o0;
            *reinterpret_cast<float4*>(C + base + 4) = o1;
        }
    } else {
        const int bglob = (rowBase >> 5) + (ty >> 2);
        float part = 0.0f;
#pragma unroll
        for (int j = 0; j < 8; j++) {
            int c = colBase + tx * 8 + j;
            float h = hs[(size_t)bglob * H_SZ + c];
            float s = 1.0f - h * h;
#pragma unroll
            for (int i = 0; i < 8; i++) {
                int d = (ty * 8 + i) & 31;
                part += W3p[d * H_SZ + c] * (acc[i][j] * s);
            }
        }
        red[tid] = part;
        __syncthreads();
        if (tid < 4) {
            float ssum = 0.0f;
#pragma unroll 8
            for (int t = 0; t < 64; t++) ssum += red[tid * 64 + t];
            // unique (jtile, sample) slot -> deterministic, no atomics
            g_tpart[blockIdx.x * B_SZ + (rowBase >> 5) + tid] = ssum;
        }
    }
}

// ---------------- small kernels ----------------

// h1 = tanh([z|t] @ W0^T + b0)
__global__ void layer0_kernel(const float* __restrict__ t, const float* __restrict__ z,
                              const float* __restrict__ W0, const float* __restrict__ b0,
                              float* __restrict__ h1)
{
    int idx = blockIdx.x * blockDim.x + threadIdx.x;   // B*H
    int j = idx & (H_SZ - 1);
    int b = idx >> 10;
    const float* w  = W0 + j * 33;
    const float* zr = z + b * D_SZ;
    float acc = b0[j] + t[0] * w[32];
#pragma unroll
    for (int d = 0; d < 32; d++) acc = fmaf(zr[d], w[d], acc);
    h1[idx] = tanhf(acc);
}

// out = h3 @ W3^T + b3
__global__ void out_kernel(const float* __restrict__ h3, const float* __restrict__ W3,
                           const float* __restrict__ b3, float* __restrict__ out)
{
    int idx = blockIdx.x * blockDim.x + threadIdx.x;   // B*D
    int d = idx & 31;
    int b = idx >> 5;
    const float* h = h3 + (size_t)b * H_SZ;
    const float* w = W3 + (size_t)d * H_SZ;
    float acc = 0.0f;
#pragma unroll 8
    for (int k = 0; k < H_SZ; k++) acc = fmaf(h[k], w[k], acc);
    out[idx] = acc + b3[d];
}

// divv[b] = -(sum of 8 j-tile partials)
__global__ void fin_kernel(float* __restrict__ out)
{
    int b = blockIdx.x * blockDim.x + threadIdx.x;
    if (b < B_SZ) {
        float s = 0.0f;
#pragma unroll
        for (int x = 0; x < 8; x++) s += g_tpart[x * B_SZ + b];
        out[B_SZ * D_SZ + b] = -s;
    }
}

// ---------------- launch ----------------
extern "C" void kernel_launch(void* const* d_in, const int* in_sizes, int n_in,
                              void* d_out, int out_size)
{
    const float* t  = (const float*)d_in[0];
    const float* z  = (const float*)d_in[1];
    const float* W0 = (const float*)d_in[2];
    const float* b0 = (const float*)d_in[3];
    const float* W1 = (const float*)d_in[4];
    const float* b1 = (const float*)d_in[5];
    const float* W2 = (const float*)d_in[6];
    const float* b2 = (const float*)d_in[7];
    const float* W3 = (const float*)d_in[8];
    const float* b3 = (const float*)d_in[9];
    float* out = (float*)d_out;

    float *ph1, *ph2, *ph3, *pU2;
    cudaGetSymbolAddress((void**)&ph1, g_h1);
    cudaGetSymbolAddress((void**)&ph2, g_h2);
    cudaGetSymbolAddress((void**)&ph3, g_h3);
    cudaGetSymbolAddress((void**)&pU2, g_U2);

    // forward
    layer0_kernel<<<(B_SZ * H_SZ) / 256, 256>>>(t, z, W0, b0, ph1);
    dim3 gF(H_SZ / BN, B_SZ / BM);           // (8, 32)
    gemm_kernel<0><<<gF, 256>>>(ph1, W1, b1, nullptr, nullptr, nullptr, ph2);
    gemm_kernel<0><<<gF, 256>>>(ph2, W2, b2, nullptr, nullptr, nullptr, ph3);
    out_kernel<<<(B_SZ * D_SZ) / 256, 256>>>(ph3, W3, b3, out);

    // tangent (JVP) chain: U2 = (1-h2^2) .* ((a1 .* W0') @ W1^T); trace from W2/W3
    dim3 gT(H_SZ / BN, MT / BM);             // (8, 1024)
    gemm_kernel<1><<<gT, 256>>>(ph1, W1, nullptr, ph2, W0, nullptr, pU2);
    gemm_kernel<2><<<gT, 256>>>(pU2, W2, nullptr, ph3, nullptr, W3, nullptr);

    fin_kernel<<<(B_SZ + 255) / 256, 256>>>(out);
}